// round 15
// baseline (speedup 1.0000x reference)
#include <cuda_runtime.h>
#include <cuda_fp16.h>
#include <math.h>
#include <stdint.h>

// x: (8,4096,512) -> N=32768, D=512 ; embed: (1,8192,512) -> C=8192
// Outputs (float32, concatenated in d_out):
//   quantize 16,777,216 | embed_ind 32,768 | new_embed 4,194,304 | new_cs 8,192

#define N_TOK   32768
#define C_CODES 8192
#define D_DIM   512
#define ONE_MINUS_DECAY 0.2f
#define CAND_THR 6.0e-3f

// -------- device scratch ----------------------------------------------------
__device__ float  g_embed_n[C_CODES * D_DIM];   // normalized codebook fp32
__device__ float  g_xn[N_TOK * D_DIM];          // normalized tokens fp32
__device__ __half g_en_h[C_CODES * D_DIM];      // fp16 codebook
__device__ __half g_xn_h[N_TOK * D_DIM];        // fp16 tokens
__device__ float  g_embed_sum[C_CODES * D_DIM];
__device__ float  g_bins[C_CODES];
__device__ int    g_ind[N_TOK];
__device__ float  g_candv[N_TOK * 48];          // 16 thr x (v1,v2,v3)
__device__ int    g_candi[N_TOK * 32];          // 16 thr x (i1,i2)
__device__ int    g_hard[N_TOK];
__device__ int    g_n_hard;

// -------- helpers -----------------------------------------------------------
__device__ __forceinline__ float block_reduce_sum_128(float v) {
    #pragma unroll
    for (int o = 16; o > 0; o >>= 1) v += __shfl_xor_sync(0xffffffffu, v, o);
    __shared__ float sp[4];
    int w = threadIdx.x >> 5, l = threadIdx.x & 31;
    if (l == 0) sp[w] = v;
    __syncthreads();
    if (threadIdx.x == 0) sp[0] = sp[0] + sp[1] + sp[2] + sp[3];
    __syncthreads();
    return sp[0];
}

// Reference-faithful sum of squares (XLA:CPU aarch64 VF=4 IC=2 order).
__device__ __forceinline__ float mimic_sumsq_512(const float* __restrict__ s) {
    float p0 = 0.f, p1 = 0.f, p2 = 0.f, p3 = 0.f;
    float p4 = 0.f, p5 = 0.f, p6 = 0.f, p7 = 0.f;
    #pragma unroll 4
    for (int j = 0; j < D_DIM; j += 8) {
        p0 = fmaf(s[j + 0], s[j + 0], p0);
        p1 = fmaf(s[j + 1], s[j + 1], p1);
        p2 = fmaf(s[j + 2], s[j + 2], p2);
        p3 = fmaf(s[j + 3], s[j + 3], p3);
        p4 = fmaf(s[j + 4], s[j + 4], p4);
        p5 = fmaf(s[j + 5], s[j + 5], p5);
        p6 = fmaf(s[j + 6], s[j + 6], p6);
        p7 = fmaf(s[j + 7], s[j + 7], p7);
    }
    float v0 = p0 + p4, v1 = p1 + p5, v2 = p2 + p6, v3 = p3 + p7;
    return (v0 + v2) + (v1 + v3);
}

// Exact sequential-k fp32 chain (identical order to the R5-passing GEMM).
__device__ __forceinline__ float exact_dot(int row, int c) {
    const float4* xa = reinterpret_cast<const float4*>(g_xn + (size_t)row * D_DIM);
    const float4* eb = reinterpret_cast<const float4*>(g_embed_n + (size_t)c * D_DIM);
    float acc = 0.f;
    #pragma unroll 8
    for (int k = 0; k < D_DIM / 4; k++) {
        float4 a = xa[k], b = eb[k];
        acc = fmaf(a.x, b.x, acc);
        acc = fmaf(a.y, b.y, acc);
        acc = fmaf(a.z, b.z, acc);
        acc = fmaf(a.w, b.w, acc);
    }
    return acc;
}

// ============================================================================
// Kernel 1: normalize codebook (fp32 div, clip) + fp16 copy + zero bufs.
// ============================================================================
__global__ void norm_embed_kernel(const float* __restrict__ embed) {
    __shared__ float srow[D_DIM];
    __shared__ float s_norm;
    int c = blockIdx.x, t = threadIdx.x;
    float4 e = reinterpret_cast<const float4*>(embed + (size_t)c * D_DIM)[t];
    reinterpret_cast<float4*>(srow)[t] = e;
    __syncthreads();
    if (t == 0) {
        float nrm = sqrtf(mimic_sumsq_512(srow));
        if (nrm < 1e-12f) nrm = 1e-12f;
        s_norm = nrm;
    }
    __syncthreads();
    float nrm = s_norm;
    float4 en = make_float4(__fdiv_rn(e.x, nrm), __fdiv_rn(e.y, nrm),
                            __fdiv_rn(e.z, nrm), __fdiv_rn(e.w, nrm));
    reinterpret_cast<float4*>(g_embed_n + (size_t)c * D_DIM)[t] = en;
    __half2 h0 = __floats2half2_rn(en.x, en.y);
    __half2 h1 = __floats2half2_rn(en.z, en.w);
    *reinterpret_cast<__half2*>(g_en_h + (size_t)c * D_DIM + t * 4)     = h0;
    *reinterpret_cast<__half2*>(g_en_h + (size_t)c * D_DIM + t * 4 + 2) = h1;
    reinterpret_cast<float4*>(g_embed_sum + (size_t)c * D_DIM)[t] =
        make_float4(0.f, 0.f, 0.f, 0.f);
    if (t == 0) {
        g_bins[c] = 0.f;
        if (c == 0) g_n_hard = 0;
    }
}

// ============================================================================
// Kernel 1b: normalize tokens + fp16 copy.
// ============================================================================
__global__ void norm_x_kernel(const float* __restrict__ X) {
    __shared__ float srow[D_DIM];
    __shared__ float s_norm;
    int n = blockIdx.x, t = threadIdx.x;
    float4 xv = reinterpret_cast<const float4*>(X + (size_t)n * D_DIM)[t];
    reinterpret_cast<float4*>(srow)[t] = xv;
    __syncthreads();
    if (t == 0) {
        float nrm = sqrtf(mimic_sumsq_512(srow));
        if (nrm < 1e-12f) nrm = 1e-12f;
        s_norm = nrm;
    }
    __syncthreads();
    float nrm = s_norm;
    float4 xn = make_float4(__fdiv_rn(xv.x, nrm), __fdiv_rn(xv.y, nrm),
                            __fdiv_rn(xv.z, nrm), __fdiv_rn(xv.w, nrm));
    reinterpret_cast<float4*>(g_xn + (size_t)n * D_DIM)[t] = xn;
    __half2 h0 = __floats2half2_rn(xn.x, xn.y);
    __half2 h1 = __floats2half2_rn(xn.z, xn.w);
    *reinterpret_cast<__half2*>(g_xn_h + (size_t)n * D_DIM + t * 4)     = h0;
    *reinterpret_cast<__half2*>(g_xn_h + (size_t)n * D_DIM + t * 4 + 2) = h1;
}

// Dummy no-op kernel: occupies launch slot 3 so the GEMM is launch 4,
// which is the launch ncu captures (-s/-c bounds).
__global__ void dummy_kernel() {}

// ============================================================================
// Kernel 2: fp16 HFMA2 GEMM + per-row candidate top-lists.
// Same block structure as the validated R12 kernel, engine swapped to
// half2 fma (2 MACs/instr, rt-2 fma pipe): BM=BN=128, BK=16, 256 thr,
// 8x8 microtile as 8x4 half2 pairs. A stored as duplicated (a,a) half2 so
// broadcast pairs load pre-packed; B columns pair naturally.
// Full 512-k dot accumulated in half2 (err ~6e-4 worst; CAND_THR=6e-3).
// ============================================================================
#define BM 128
#define BN 128
#define BK 16

__global__ __launch_bounds__(256, 2)
void gemm_cand_kernel() {
    __shared__ __half As[BK][2 * BM];   // dup pairs: 8 KB
    __shared__ __half Bs[BK][BN];       // 4 KB

    const int tid  = threadIdx.x;
    const int tcol = tid & 15;
    const int trow = tid >> 4;
    const int m0 = trow * 8;
    const int n0 = tcol * 8;
    const int rowBase = blockIdx.x * BM;
    const __half* __restrict__ XH = g_xn_h;
    const __half* __restrict__ EH = g_en_h;

    // global-load mapping: 256 threads, each loads 8 halves (16B) per tile
    const int glr = tid >> 1;          // 0..127 (row or col)
    const int glk = (tid & 1) * 8;     // k offset 0 or 8

    float v1[8], v2[8], v3[8];
    int   i1[8], i2[8];
    #pragma unroll
    for (int i = 0; i < 8; i++) {
        v1[i] = -3.4e38f; v2[i] = -3.4e38f; v3[i] = -3.4e38f;
        i1[i] = 0; i2[i] = 0;
    }

    for (int nt = 0; nt < C_CODES / BN; nt++) {
        const int colBase = nt * BN;

        __half2 acc2[8][4];
        #pragma unroll
        for (int i = 0; i < 8; i++)
            #pragma unroll
            for (int jp = 0; jp < 4; jp++)
                acc2[i][jp] = __float2half2_rn(0.f);

        for (int kt = 0; kt < D_DIM / BK; kt++) {
            const int k0 = kt * BK;
            // ---- A tile: row glr, k [k0+glk, +8) -> duplicated pairs
            {
                uint4 av = *reinterpret_cast<const uint4*>(
                    XH + (size_t)(rowBase + glr) * D_DIM + k0 + glk);
                const __half* ah = reinterpret_cast<const __half*>(&av);
                #pragma unroll
                for (int j = 0; j < 8; j++)
                    *reinterpret_cast<__half2*>(&As[glk + j][2 * glr]) =
                        __half2half2(ah[j]);
            }
            // ---- B tile: col glr, k [k0+glk, +8)
            {
                uint4 bv = *reinterpret_cast<const uint4*>(
                    EH + (size_t)(colBase + glr) * D_DIM + k0 + glk);
                const __half* bh = reinterpret_cast<const __half*>(&bv);
                #pragma unroll
                for (int j = 0; j < 8; j++)
                    Bs[glk + j][glr] = bh[j];
            }
            __syncthreads();

            #pragma unroll
            for (int k = 0; k < BK; k++) {
                uint4 a0 = *reinterpret_cast<const uint4*>(&As[k][2 * m0]);
                uint4 a1 = *reinterpret_cast<const uint4*>(&As[k][2 * m0 + 8]);
                const __half2* ad0 = reinterpret_cast<const __half2*>(&a0);
                const __half2* ad1 = reinterpret_cast<const __half2*>(&a1);
                __half2 a[8] = {ad0[0], ad0[1], ad0[2], ad0[3],
                                ad1[0], ad1[1], ad1[2], ad1[3]};
                uint4 bb = *reinterpret_cast<const uint4*>(&Bs[k][n0]);
                const __half2* bp = reinterpret_cast<const __half2*>(&bb);
                __half2 b[4] = {bp[0], bp[1], bp[2], bp[3]};
                #pragma unroll
                for (int i = 0; i < 8; i++)
                    #pragma unroll
                    for (int jp = 0; jp < 4; jp++)
                        acc2[i][jp] = __hfma2(a[i], b[jp], acc2[i][jp]);
            }
            __syncthreads();
        }

        // fold tile into per-row top-2 + v3 sentinel (ascending col index)
        #pragma unroll
        for (int jp = 0; jp < 4; jp++) {
            const int c0 = colBase + n0 + 2 * jp;
            #pragma unroll
            for (int i = 0; i < 8; i++) {
                float lo = __low2float(acc2[i][jp]);
                float hi = __high2float(acc2[i][jp]);
                if (lo > v1[i]) {
                    v3[i] = v2[i]; v2[i] = v1[i]; i2[i] = i1[i];
                    v1[i] = lo; i1[i] = c0;
                } else if (lo > v2[i]) {
                    v3[i] = v2[i]; v2[i] = lo; i2[i] = c0;
                } else if (lo > v3[i]) v3[i] = lo;
                if (hi > v1[i]) {
                    v3[i] = v2[i]; v2[i] = v1[i]; i2[i] = i1[i];
                    v1[i] = hi; i1[i] = c0 + 1;
                } else if (hi > v2[i]) {
                    v3[i] = v2[i]; v2[i] = hi; i2[i] = c0 + 1;
                } else if (hi > v3[i]) v3[i] = hi;
            }
        }
    }

    #pragma unroll
    for (int i = 0; i < 8; i++) {
        const int r = rowBase + m0 + i;
        g_candv[(size_t)r * 48 + tcol * 3 + 0] = v1[i];
        g_candv[(size_t)r * 48 + tcol * 3 + 1] = v2[i];
        g_candv[(size_t)r * 48 + tcol * 3 + 2] = v3[i];
        g_candi[(size_t)r * 32 + tcol * 2 + 0] = i1[i];
        g_candi[(size_t)r * 32 + tcol * 2 + 1] = i2[i];
    }
}

// ============================================================================
// Kernel 2b: resolve. Values are approximate cosines (absolute units):
// cut = M - CAND_THR. v3 >= cut -> possible hidden candidates -> hard list.
// ============================================================================
__global__ void resolve_pick_kernel() {
    int r = blockIdx.x * 128 + threadIdx.x;
    if (r >= N_TOK) return;
    float v[48]; int ci[32];
    #pragma unroll
    for (int q = 0; q < 48; q++) v[q] = g_candv[(size_t)r * 48 + q];
    #pragma unroll
    for (int q = 0; q < 32; q++) ci[q] = g_candi[(size_t)r * 32 + q];

    float M = -3.4e38f;
    #pragma unroll
    for (int t = 0; t < 16; t++) M = fmaxf(M, v[t * 3]);
    float cut = M - CAND_THR;

    bool flag = false;
    #pragma unroll
    for (int t = 0; t < 16; t++)
        if (v[t * 3 + 2] >= cut) flag = true;
    if (flag) {
        int slot = atomicAdd(&g_n_hard, 1);
        g_hard[slot] = r;
        return;
    }

    int cand[32]; int nc = 0;
    #pragma unroll
    for (int t = 0; t < 16; t++) {
        if (v[t * 3 + 0] >= cut) cand[nc++] = ci[t * 2 + 0];
        if (v[t * 3 + 1] >= cut) cand[nc++] = ci[t * 2 + 1];
    }
    if (nc == 1) { g_ind[r] = cand[0]; return; }

    float bev = -3.4e38f; int bi = 0x7fffffff;
    for (int q = 0; q < nc; q++) {
        float d = exact_dot(r, cand[q]);
        if (d > bev || (d == bev && cand[q] < bi)) { bev = d; bi = cand[q]; }
    }
    g_ind[r] = bi;
}

// Full exact scan for flagged rows: one block per list entry (strided).
__global__ __launch_bounds__(256, 4)
void resolve_hard_kernel() {
    __shared__ float s_v[256];
    __shared__ int   s_i[256];
    const int nh = g_n_hard;
    for (int it = blockIdx.x; it < nh; it += gridDim.x) {
        const int r = g_hard[it];
        float bv = -3.4e38f; int bi = 0x7fffffff;
        for (int c = threadIdx.x; c < C_CODES; c += 256) {
            float d = exact_dot(r, c);
            if (d > bv) { bv = d; bi = c; }     // ascending c -> first idx
        }
        s_v[threadIdx.x] = bv; s_i[threadIdx.x] = bi;
        __syncthreads();
        for (int s = 128; s > 0; s >>= 1) {
            if (threadIdx.x < s) {
                float ov = s_v[threadIdx.x + s]; int oi = s_i[threadIdx.x + s];
                if (ov > s_v[threadIdx.x] ||
                    (ov == s_v[threadIdx.x] && oi < s_i[threadIdx.x])) {
                    s_v[threadIdx.x] = ov; s_i[threadIdx.x] = oi;
                }
            }
            __syncthreads();
        }
        if (threadIdx.x == 0) g_ind[r] = s_i[0];
        __syncthreads();
    }
}

// ============================================================================
// Kernel 3: per-token epilogue (gather quantize, scatter normalized x + bins).
// ============================================================================
__global__ void epilogue_kernel(const float* __restrict__ embed,
                                float* __restrict__ out_q,
                                float* __restrict__ out_ind) {
    int n = blockIdx.x, t = threadIdx.x;
    int c = g_ind[n];
    float4 xn = reinterpret_cast<const float4*>(g_xn + (size_t)n * D_DIM)[t];
    float* es = g_embed_sum + (size_t)c * D_DIM + t * 4;
    atomicAdd(es + 0, xn.x);
    atomicAdd(es + 1, xn.y);
    atomicAdd(es + 2, xn.z);
    atomicAdd(es + 3, xn.w);
    float4 ev = reinterpret_cast<const float4*>(embed + (size_t)c * D_DIM)[t];
    reinterpret_cast<float4*>(out_q + (size_t)n * D_DIM)[t] = ev;
    if (t == 0) {
        out_ind[n] = (float)c;
        atomicAdd(&g_bins[c], 1.0f);
    }
}

// ============================================================================
// Kernel 4: per-code EMA finalize.
// ============================================================================
__global__ void finalize_kernel(const float* __restrict__ embed,
                                const float* __restrict__ cluster_size,
                                float* __restrict__ out_embed,
                                float* __restrict__ out_cs) {
    int c = blockIdx.x, t = threadIdx.x;
    float b = g_bins[c];
    bool zero = (b == 0.0f);
    float inv_b = 1.0f / (zero ? 1.0f : b);
    float4 es = reinterpret_cast<const float4*>(g_embed_sum + (size_t)c * D_DIM)[t];
    float4 v = make_float4(es.x * inv_b, es.y * inv_b, es.z * inv_b, es.w * inv_b);
    float ss = v.x * v.x + v.y * v.y + v.z * v.z + v.w * v.w;
    ss = block_reduce_sum_128(ss);
    float rn = 1.0f / fmaxf(sqrtf(ss), 1e-12f);
    float4 en;
    if (zero) en = reinterpret_cast<const float4*>(g_embed_n + (size_t)c * D_DIM)[t];
    else      en = make_float4(v.x * rn, v.y * rn, v.z * rn, v.w * rn);
    float4 e = reinterpret_cast<const float4*>(embed + (size_t)c * D_DIM)[t];
    reinterpret_cast<float4*>(out_embed + (size_t)c * D_DIM)[t] =
        make_float4(e.x + ONE_MINUS_DECAY * (en.x - e.x),
                    e.y + ONE_MINUS_DECAY * (en.y - e.y),
                    e.z + ONE_MINUS_DECAY * (en.z - e.z),
                    e.w + ONE_MINUS_DECAY * (en.w - e.w));
    if (t == 0) {
        float cs = cluster_size[c];
        out_cs[c] = cs + ONE_MINUS_DECAY * (b - cs);
    }
}

// ============================================================================
extern "C" void kernel_launch(void* const* d_in, const int* in_sizes, int n_in,
                              void* d_out, int out_size) {
    const float* x     = (const float*)d_in[0];
    const float* embed = (const float*)d_in[1];
    const float* cs    = (const float*)d_in[2];

    float* out       = (float*)d_out;
    float* out_q     = out;
    float* out_ind   = out + 16777216;
    float* out_embed = out + 16777216 + 32768;
    float* out_cs    = out + 16777216 + 32768 + 4194304;

    norm_embed_kernel<<<C_CODES, 128>>>(embed);     // launch 1
    norm_x_kernel<<<N_TOK, 128>>>(x);               // launch 2
    dummy_kernel<<<1, 32>>>();                      // launch 3 (profiling pad)
    gemm_cand_kernel<<<N_TOK / BM, 256>>>();        // launch 4 <- ncu capture
    resolve_pick_kernel<<<N_TOK / 128, 128>>>();    // launch 5
    resolve_hard_kernel<<<148, 256>>>();            // launch 6
    epilogue_kernel<<<N_TOK, 128>>>(embed, out_q, out_ind);
    finalize_kernel<<<C_CODES, 128>>>(embed, cs, out_embed, out_cs);
}